// round 4
// baseline (speedup 1.0000x reference)
#include <cuda_runtime.h>

#define NEGV (-1000000000.0f)
#define SROW 129   // padded smem row stride (odd => conflict-free j-varying access)

__global__ __launch_bounds__(512, 1)
void GNN_kernel(const float* __restrict__ team_obs,
                const float* __restrict__ target_obs,
                const float* __restrict__ team_mask,
                const float* __restrict__ ltm,
                const float* __restrict__ W_emb,
                const float* __restrict__ b_emb,
                const float* __restrict__ Wl1, const float* __restrict__ Wr1,
                const float* __restrict__ att1, const float* __restrict__ b1,
                const float* __restrict__ Wl2, const float* __restrict__ Wr2,
                const float* __restrict__ att2, const float* __restrict__ b2,
                const float* __restrict__ Wl3, const float* __restrict__ Wr3,
                const float* __restrict__ att3, const float* __restrict__ b3,
                const float* __restrict__ ln1g, const float* __restrict__ ln1b,
                const float* __restrict__ ln2g, const float* __restrict__ ln2b,
                float* __restrict__ outg)
{
    extern __shared__ float sm[];
    float* bufA = sm;                  // 64*129
    float* bufB = bufA + 64 * SROW;    // 64*129
    float* bufC = bufB + 64 * SROW;    // 64*129
    float* eBuf = bufC + 64 * SROW;    // 64*64*4 = 16384 (layout: (i*64+j)*H + h)
    float* attS = eBuf + 16384;        // 128
    float* invS = attS + 128;          // 256  (j*H + h)
    float* finS = invS + 256;          // 64*16 = 1024
    float* impS = finS + 1024;         // 64

    const int tid = threadIdx.x;
    const int b   = blockIdx.x;

    // ---------------- Phase 0: build fin (64x16) + importance flags ----------------
    if (tid < 64) {
        float ok;
        if (tid < 16) ok = (team_mask[b * 32 + tid] != NEGV) ? 1.0f : 0.0f;
        else          ok = (ltm[b * 49 + (tid - 16)] != 0.0f) ? 1.0f : 0.0f;
        impS[tid] = ok;
    }
    for (int idx = tid; idx < 1024; idx += 512) {
        int m = idx >> 4, k = idx & 15;
        float v = 0.0f;
        if (m < 16) {
            if (k < 14) v = team_obs[(b * 16 + m) * 14 + k];
        } else {
            int t = m - 16;
            const float* src = &target_obs[(b * 48 + t) * 15];
            if (k < 12)       v = src[k];
            else if (k == 14) v = src[12];
            else if (k == 15) v = src[13];
            // k==12,13 stay zero (inserted zero columns)
        }
        finS[idx] = v;
    }
    __syncthreads();

    // ---------------- Phase 1: embedding h = fin @ W_emb + b_emb -> bufA ----------------
    {
        int f = tid & 127, g = tid >> 7;
        float wc[16];
#pragma unroll
        for (int k = 0; k < 16; k++) wc[k] = W_emb[k * 128 + f];
        float bb = b_emb[f];
#pragma unroll 4
        for (int t = 0; t < 16; t++) {
            int m = g + 4 * t;
            float acc = bb;
            const float* fr = &finS[m * 16];
#pragma unroll
            for (int k = 0; k < 16; k++) acc = fmaf(fr[k], wc[k], acc);
            bufA[m * SROW + f] = acc;
        }
    }
    __syncthreads();

    const float* WlP[3] = { Wl1, Wl2, Wl3 };
    const float* WrP[3] = { Wr1, Wr2, Wr3 };
    const float* atP[3] = { att1, att2, att3 };
    const float* biP[3] = { b1, b2, b3 };
    const float* lgP[2] = { ln1g, ln2g };
    const float* lbP[2] = { ln1b, ln2b };

    float* hs  = bufA;
    float* xls = bufB;
    float* xrs = bufC;

    for (int L = 0; L < 3; L++) {
        const int Fout = (L == 2) ? 64 : 128;
        const int H    = (L == 2) ? 1  : 4;
        const int C    = (L == 2) ? 64 : 32;

        if (tid < H * C) attS[tid] = atP[L][tid];

        // ---- GEMMs: xl = h @ Wl, xr = h @ Wr (K = 128) ----
        {
            int f      = tid % Fout;
            int which  = tid / Fout;
            int half   = 256 / Fout;            // 2 (F=128) or 4 (F=64)
            int matSel = (which >= half);
            int rows   = 64 / half;             // 32 or 16
            int rstart = (matSel ? which - half : which) * rows;
            const float* W = matSel ? WrP[L] : WlP[L];
            float* dst     = matSel ? xrs : xls;
            for (int m0 = rstart; m0 < rstart + rows; m0 += 8) {
                float a0=0,a1=0,a2=0,a3=0,a4=0,a5=0,a6=0,a7=0;
                const float* h0 = &hs[(m0+0)*SROW];
                const float* h1 = &hs[(m0+1)*SROW];
                const float* h2 = &hs[(m0+2)*SROW];
                const float* h3 = &hs[(m0+3)*SROW];
                const float* h4 = &hs[(m0+4)*SROW];
                const float* h5 = &hs[(m0+5)*SROW];
                const float* h6 = &hs[(m0+6)*SROW];
                const float* h7 = &hs[(m0+7)*SROW];
#pragma unroll 4
                for (int k = 0; k < 128; k++) {
                    float w = W[k * Fout + f];
                    a0 = fmaf(h0[k], w, a0);
                    a1 = fmaf(h1[k], w, a1);
                    a2 = fmaf(h2[k], w, a2);
                    a3 = fmaf(h3[k], w, a3);
                    a4 = fmaf(h4[k], w, a4);
                    a5 = fmaf(h5[k], w, a5);
                    a6 = fmaf(h6[k], w, a6);
                    a7 = fmaf(h7[k], w, a7);
                }
                dst[(m0+0)*SROW+f] = a0;
                dst[(m0+1)*SROW+f] = a1;
                dst[(m0+2)*SROW+f] = a2;
                dst[(m0+3)*SROW+f] = a3;
                dst[(m0+4)*SROW+f] = a4;
                dst[(m0+5)*SROW+f] = a5;
                dst[(m0+6)*SROW+f] = a6;
                dst[(m0+7)*SROW+f] = a7;
            }
        }
        __syncthreads();

        // ---- attention scores e[i][j][h] = sum_c leaky(xl[i]+xr[j]) * att ----
        {
            int lane = tid & 31, w = tid >> 5;
            for (int ii = 0; ii < 4; ii++) {
                int i = w * 4 + ii;
                for (int h = 0; h < H; h++) {
                    float acc0 = 0.0f, acc1 = 0.0f;
                    int base = h * C;
                    const float* xli = &xls[i * SROW + base];
                    const float* xr0 = &xrs[lane * SROW + base];
                    const float* xr1 = &xrs[(lane + 32) * SROW + base];
                    const float* at  = &attS[base];
#pragma unroll 8
                    for (int c = 0; c < C; c++) {
                        float xlv = xli[c];
                        float av  = at[c];
                        float t0  = xlv + xr0[c];
                        float t1  = xlv + xr1[c];
                        acc0 = fmaf(fmaxf(t0, 0.2f * t0), av, acc0);
                        acc1 = fmaf(fmaxf(t1, 0.2f * t1), av, acc1);
                    }
                    eBuf[(i * 64 + lane)      * H + h] = acc0;
                    eBuf[(i * 64 + lane + 32) * H + h] = acc1;
                }
            }
        }
        __syncthreads();

        // ---- masked softmax over i (per (j,h)); store p into eBuf, 1/sum into invS ----
        if (tid < 64 * H) {
            int j = tid / H, h = tid % H;
            bool impj = (impS[j] != 0.0f);
            float mx = -3.4e38f;
            for (int i = 0; i < 64; i++) {
                float v = eBuf[(i * 64 + j) * H + h];
                bool ok = (i == j) || (impj && (impS[i] != 0.0f));
                mx = fmaxf(mx, ok ? v : NEGV);
            }
            float sum = 0.0f;
            for (int i = 0; i < 64; i++) {
                float v = eBuf[(i * 64 + j) * H + h];
                bool ok = (i == j) || (impj && (impS[i] != 0.0f));
                float p = ok ? __expf(v - mx) : 0.0f;
                eBuf[(i * 64 + j) * H + h] = p;
                sum += p;
            }
            invS[tid] = 1.0f / sum;
        }
        __syncthreads();

        // ---- aggregate: out[j][f] = (1/sum) * sum_i p[i][j][h] * xl[i][f] + bias[f] ----
        {
            int f    = tid % Fout;
            int grp  = tid / Fout;
            int nG   = 512 / Fout;             // 4 or 8
            int jPer = 64 / nG;                // 16 or 8
            int h    = f / C;
            float bv = biP[L][f];
            for (int jj = 0; jj < jPer; jj++) {
                int j = grp * jPer + jj;
                float acc = 0.0f;
#pragma unroll 4
                for (int i = 0; i < 64; i++)
                    acc = fmaf(eBuf[(i * 64 + j) * H + h], xls[i * SROW + f], acc);
                float val = acc * invS[j * H + h] + bv;
                if (L == 2) outg[(b * 64 + j) * 64 + f] = val;
                else        xrs[j * SROW + f] = val;
            }
        }

        if (L < 2) {
            __syncthreads();
            // ---- LayerNorm (biased var, eps 1e-5) + ReLU, in place on xrs ----
            const float* g  = lgP[L];
            const float* bl = lbP[L];
            int lane = tid & 31, w = tid >> 5;
            for (int t = 0; t < 4; t++) {
                int m = w + 16 * t;
                float x0 = xrs[m * SROW + lane];
                float x1 = xrs[m * SROW + lane + 32];
                float x2 = xrs[m * SROW + lane + 64];
                float x3 = xrs[m * SROW + lane + 96];
                float s = x0 + x1 + x2 + x3;
#pragma unroll
                for (int off = 16; off; off >>= 1) s += __shfl_xor_sync(0xffffffffu, s, off);
                float mean = s * (1.0f / 128.0f);
                float d0 = x0 - mean, d1 = x1 - mean, d2 = x2 - mean, d3 = x3 - mean;
                float q = d0 * d0 + d1 * d1 + d2 * d2 + d3 * d3;
#pragma unroll
                for (int off = 16; off; off >>= 1) q += __shfl_xor_sync(0xffffffffu, q, off);
                float rstd = rsqrtf(q * (1.0f / 128.0f) + 1e-5f);
                xrs[m * SROW + lane]      = fmaxf(fmaf(d0 * rstd, g[lane],      bl[lane]),      0.0f);
                xrs[m * SROW + lane + 32] = fmaxf(fmaf(d1 * rstd, g[lane + 32], bl[lane + 32]), 0.0f);
                xrs[m * SROW + lane + 64] = fmaxf(fmaf(d2 * rstd, g[lane + 64], bl[lane + 64]), 0.0f);
                xrs[m * SROW + lane + 96] = fmaxf(fmaf(d3 * rstd, g[lane + 96], bl[lane + 96]), 0.0f);
            }
            __syncthreads();
            // rotate: normalized output becomes next layer's input
            float* nh = xrs; xrs = xls; xls = hs; hs = nh;
        }
    }
}

extern "C" void kernel_launch(void* const* d_in, const int* in_sizes, int n_in,
                              void* d_out, int out_size) {
    (void)in_sizes; (void)n_in; (void)out_size;
    const size_t smem = (size_t)(3 * 64 * SROW + 16384 + 128 + 256 + 1024 + 64) * sizeof(float);
    cudaFuncSetAttribute(GNN_kernel, cudaFuncAttributeMaxDynamicSharedMemorySize, (int)smem);
    GNN_kernel<<<128, 512, smem>>>(
        (const float*)d_in[0],  (const float*)d_in[1],  (const float*)d_in[2],
        (const float*)d_in[3],  (const float*)d_in[4],  (const float*)d_in[5],
        (const float*)d_in[6],  (const float*)d_in[7],  (const float*)d_in[8],
        (const float*)d_in[9],  (const float*)d_in[10], (const float*)d_in[11],
        (const float*)d_in[12], (const float*)d_in[13], (const float*)d_in[14],
        (const float*)d_in[15], (const float*)d_in[16], (const float*)d_in[17],
        (const float*)d_in[18], (const float*)d_in[19], (const float*)d_in[20],
        (const float*)d_in[21], (float*)d_out);
}

// round 8
// speedup vs baseline: 2.7299x; 2.7299x over previous
#include <cuda_runtime.h>

#define NEGV (-1000000000.0f)
#define HTS 66    // hT row stride (transposed h: hT[k][m])
#define XS  130   // natural xl/xr row stride (even => LDS.64-aligned, conflict-free lane-stride)

typedef unsigned long long u64;

__device__ __forceinline__ u64 ld2(const float* p) {
    return *reinterpret_cast<const u64*>(p);
}
__device__ __forceinline__ u64 fma2(u64 a, u64 b, u64 c) {
    u64 d; asm("fma.rn.f32x2 %0,%1,%2,%3;" : "=l"(d) : "l"(a), "l"(b), "l"(c)); return d;
}
__device__ __forceinline__ u64 add2(u64 a, u64 b) {
    u64 d; asm("add.rn.f32x2 %0,%1,%2;" : "=l"(d) : "l"(a), "l"(b)); return d;
}
__device__ __forceinline__ u64 abs2(u64 a) {
    return a & 0x7FFFFFFF7FFFFFFFull;   // clear sign bits of both halves (2x LOP3)
}
__device__ __forceinline__ u64 dup2(float x) {
    u64 d; asm("mov.b64 %0,{%1,%1};" : "=l"(d) : "f"(x)); return d;
}
__device__ __forceinline__ float2 unp2(u64 a) {
    float2 r; asm("mov.b64 {%0,%1},%2;" : "=f"(r.x), "=f"(r.y) : "l"(a)); return r;
}

template<int Fout, int H, bool FINAL>
__device__ __forceinline__ void layer_body(
    float* __restrict__ hT, float* __restrict__ xln, float* __restrict__ xrn,
    float* __restrict__ eBuf, float* __restrict__ SLa, float* __restrict__ SRa,
    float* __restrict__ attS, float* __restrict__ att04S, float* __restrict__ biasS,
    float* __restrict__ invS, const float* __restrict__ impS,
    const float* __restrict__ Wl, const float* __restrict__ Wr,
    const float* __restrict__ att, const float* __restrict__ bias,
    const float* __restrict__ lng, const float* __restrict__ lnb,
    float* __restrict__ outg, int b, int tid)
{
    constexpr int C = Fout / H;

    // ---- stage att / 0.4*att / bias (read only after next sync) ----
    if (tid < Fout) {
        float a = att[tid];
        attS[tid] = a; att04S[tid] = 0.4f * a; biasS[tid] = bias[tid];
    }

    // ---- dual GEMM: xl = h @ Wl, xr = h @ Wr  (h read transposed, row-pair packed) ----
    {
        constexpr int NFS   = Fout / 2;      // f-slots per matrix-half: 64 or 32
        constexpr int nGrp  = 512 / NFS;     // 8 or 16
        constexpr int halfG = nGrp / 2;      // 4 or 8
        constexpr int rows  = 64 / halfG;    // 16 or 8
        constexpr int RP    = rows / 2;      // row-pairs: 8 or 4
        int fslot = tid % NFS;
        int grp   = tid / NFS;
        bool matSel = grp >= halfG;
        int sub     = matSel ? grp - halfG : grp;
        int rstart  = sub * rows;
        const float* W = matSel ? Wr : Wl;
        float* dst     = matSel ? xrn : xln;
        int f0 = fslot, f1 = fslot + NFS;
        u64 acc0[RP], acc1[RP];
        #pragma unroll
        for (int p = 0; p < RP; p++) { acc0[p] = 0ull; acc1[p] = 0ull; }
        #pragma unroll 1
        for (int kk = 0; kk < 128; kk += 8) {
            float w0[8], w1[8];
            #pragma unroll
            for (int q = 0; q < 8; q++) {
                w0[q] = W[(kk + q) * Fout + f0];
                w1[q] = W[(kk + q) * Fout + f1];
            }
            #pragma unroll
            for (int q = 0; q < 8; q++) {
                const float* hk = &hT[(kk + q) * HTS + rstart];
                u64 wd0 = dup2(w0[q]), wd1 = dup2(w1[q]);
                #pragma unroll
                for (int p = 0; p < RP; p++) {
                    u64 h2 = ld2(hk + 2 * p);
                    acc0[p] = fma2(h2, wd0, acc0[p]);
                    acc1[p] = fma2(h2, wd1, acc1[p]);
                }
            }
        }
        #pragma unroll
        for (int p = 0; p < RP; p++) {
            float2 v0 = unp2(acc0[p]), v1 = unp2(acc1[p]);
            int r = rstart + 2 * p;
            dst[r * XS + f0]       = v0.x;
            dst[(r + 1) * XS + f0] = v0.y;
            dst[r * XS + f1]       = v1.x;
            dst[(r + 1) * XS + f1] = v1.y;
        }
    }
    __syncthreads();

    // ---- SL_i[h] = sum_c xl*att ; SR_j[h] = sum_c xr*att ----
    if (tid < 128 * H) {
        int i   = tid & 63;
        int hm  = tid >> 6;
        int h   = hm & (H - 1);
        int mat = hm / H;
        const float* x = (mat ? xrn : xln) + i * XS + h * C;
        const float* a = attS + h * C;
        u64 acc = 0ull;
        #pragma unroll
        for (int c = 0; c < C; c += 2) acc = fma2(ld2(x + c), ld2(a + c), acc);
        float2 v = unp2(acc);
        (mat ? SRa : SLa)[h * 64 + i] = v.x + v.y;
    }
    __syncthreads();

    // ---- e-phase: e_ij = 0.6*(SL_i+SR_j) + sum_c |xl+xr| * (0.4*att); mask folded ----
    {
        int l = tid & 31, w = tid >> 5;
        int i0 = w * 4;
        float impj0 = impS[l], impj1 = impS[l + 32];
        #pragma unroll 1
        for (int h = 0; h < H; h++) {
            u64 acc[4][2];
            #pragma unroll
            for (int ii = 0; ii < 4; ii++) { acc[ii][0] = 0ull; acc[ii][1] = 0ull; }
            const float* a04 = att04S + h * C;
            const float* xr0 = &xrn[l * XS + h * C];
            const float* xr1 = &xrn[(l + 32) * XS + h * C];
            const float* xlb = &xln[i0 * XS + h * C];
            #pragma unroll 4
            for (int c = 0; c < C; c += 2) {
                u64 r0 = ld2(xr0 + c), r1 = ld2(xr1 + c), a2 = ld2(a04 + c);
                #pragma unroll
                for (int ii = 0; ii < 4; ii++) {
                    u64 xl2 = ld2(xlb + ii * XS + c);
                    acc[ii][0] = fma2(abs2(add2(xl2, r0)), a2, acc[ii][0]);
                    acc[ii][1] = fma2(abs2(add2(xl2, r1)), a2, acc[ii][1]);
                }
            }
            float sr0 = SRa[h * 64 + l], sr1 = SRa[h * 64 + l + 32];
            #pragma unroll
            for (int ii = 0; ii < 4; ii++) {
                int i = i0 + ii;
                float impi = impS[i];
                float sl = SLa[h * 64 + i];
                float2 t0 = unp2(acc[ii][0]), t1 = unp2(acc[ii][1]);
                float e0 = 0.6f * (sl + sr0) + (t0.x + t0.y);
                float e1 = 0.6f * (sl + sr1) + (t1.x + t1.y);
                bool ok0 = (i == l)      || (impi != 0.f && impj0 != 0.f);
                bool ok1 = (i == l + 32) || (impi != 0.f && impj1 != 0.f);
                eBuf[h * 4096 + i * 64 + l]      = ok0 ? e0 : NEGV;
                eBuf[h * 4096 + i * 64 + l + 32] = ok1 ? e1 : NEGV;
            }
        }
    }
    __syncthreads();

    // ---- softmax over i per (j,h); mask already folded (NEG entries underflow exp) ----
    if (tid < 64 * H) {
        int j = tid & 63, h = tid >> 6;
        float* col = eBuf + h * 4096 + j;
        float mx = col[0];
        #pragma unroll 8
        for (int i = 1; i < 64; i++) mx = fmaxf(mx, col[i * 64]);
        float sum = 0.f;
        #pragma unroll 8
        for (int i = 0; i < 64; i++) {
            float p = __expf(col[i * 64] - mx);
            col[i * 64] = p;
            sum += p;
        }
        invS[h * 64 + j] = 1.f / sum;
    }
    __syncthreads();

    // ---- aggregate: out[j][f] = inv_j * sum_i p_ij * xl_i[f] + bias ----
    if constexpr (!FINAL) {
        int l = tid & 31, w = tid >> 5;
        int fb = 8 * w;            // 8 f's per warp; octet never crosses an h boundary
        int h  = w >> 2;
        const float* pcol = eBuf + h * 4096;
        u64 a0[4], a1[4];
        #pragma unroll
        for (int q = 0; q < 4; q++) { a0[q] = 0ull; a1[q] = 0ull; }
        #pragma unroll 2
        for (int i = 0; i < 64; i++) {
            const float* xli = &xln[i * XS + fb];
            u64 x0 = ld2(xli), x1 = ld2(xli + 2), x2 = ld2(xli + 4), x3 = ld2(xli + 6);
            u64 pa = dup2(pcol[i * 64 + l]);
            u64 pb = dup2(pcol[i * 64 + l + 32]);
            a0[0] = fma2(x0, pa, a0[0]); a0[1] = fma2(x1, pa, a0[1]);
            a0[2] = fma2(x2, pa, a0[2]); a0[3] = fma2(x3, pa, a0[3]);
            a1[0] = fma2(x0, pb, a1[0]); a1[1] = fma2(x1, pb, a1[1]);
            a1[2] = fma2(x2, pb, a1[2]); a1[3] = fma2(x3, pb, a1[3]);
        }
        float inv0 = invS[h * 64 + l], inv1 = invS[h * 64 + l + 32];
        #pragma unroll
        for (int q = 0; q < 4; q++) {
            float2 v0 = unp2(a0[q]), v1 = unp2(a1[q]);
            int f = fb + 2 * q;
            hT[f * HTS + l]            = fmaf(v0.x, inv0, biasS[f]);
            hT[(f + 1) * HTS + l]      = fmaf(v0.y, inv0, biasS[f + 1]);
            hT[f * HTS + l + 32]       = fmaf(v1.x, inv1, biasS[f]);
            hT[(f + 1) * HTS + l + 32] = fmaf(v1.y, inv1, biasS[f + 1]);
        }
        __syncthreads();
        // ---- LayerNorm (biased var, eps 1e-5) + ReLU over hT columns ----
        {
            float g0 = lng[l], g1 = lng[l + 32], g2 = lng[l + 64], g3 = lng[l + 96];
            float bb0 = lnb[l], bb1 = lnb[l + 32], bb2 = lnb[l + 64], bb3 = lnb[l + 96];
            #pragma unroll
            for (int t = 0; t < 4; t++) {
                int m = w * 4 + t;
                float x0 = hT[l * HTS + m],        x1 = hT[(l + 32) * HTS + m];
                float x2 = hT[(l + 64) * HTS + m], x3 = hT[(l + 96) * HTS + m];
                float s = x0 + x1 + x2 + x3;
                #pragma unroll
                for (int off = 16; off; off >>= 1) s += __shfl_xor_sync(~0u, s, off);
                float mean = s * (1.f / 128.f);
                float d0 = x0 - mean, d1 = x1 - mean, d2 = x2 - mean, d3 = x3 - mean;
                float qv = d0 * d0 + d1 * d1 + d2 * d2 + d3 * d3;
                #pragma unroll
                for (int off = 16; off; off >>= 1) qv += __shfl_xor_sync(~0u, qv, off);
                float rstd = rsqrtf(qv * (1.f / 128.f) + 1e-5f);
                hT[l * HTS + m]        = fmaxf(fmaf(d0 * rstd, g0, bb0), 0.f);
                hT[(l + 32) * HTS + m] = fmaxf(fmaf(d1 * rstd, g1, bb1), 0.f);
                hT[(l + 64) * HTS + m] = fmaxf(fmaf(d2 * rstd, g2, bb2), 0.f);
                hT[(l + 96) * HTS + m] = fmaxf(fmaf(d3 * rstd, g3, bb3), 0.f);
            }
        }
        __syncthreads();
    } else {
        // final layer: Fout=64, H=1 — coalesced gmem store (lanes along f)
        int l = tid & 31, w = tid >> 5;
        #pragma unroll
        for (int jj = 0; jj < 4; jj++) {
            int j = w + 16 * jj;
            const float* pcol = eBuf + j;
            u64 acc = 0ull;
            #pragma unroll 4
            for (int i = 0; i < 64; i++)
                acc = fma2(ld2(&xln[i * XS + 2 * l]), dup2(pcol[i * 64]), acc);
            float inv = invS[j];
            float2 v = unp2(acc);
            float2 r;
            r.x = fmaf(v.x, inv, biasS[2 * l]);
            r.y = fmaf(v.y, inv, biasS[2 * l + 1]);
            *reinterpret_cast<float2*>(&outg[(b * 64 + j) * 64 + 2 * l]) = r;
        }
    }
}

__global__ __launch_bounds__(512, 1)
void GNN_kernel(const float* __restrict__ team_obs,
                const float* __restrict__ target_obs,
                const float* __restrict__ team_mask,
                const float* __restrict__ ltm,
                const float* __restrict__ W_emb,
                const float* __restrict__ b_emb,
                const float* __restrict__ Wl1, const float* __restrict__ Wr1,
                const float* __restrict__ att1, const float* __restrict__ b1,
                const float* __restrict__ Wl2, const float* __restrict__ Wr2,
                const float* __restrict__ att2, const float* __restrict__ b2,
                const float* __restrict__ Wl3, const float* __restrict__ Wr3,
                const float* __restrict__ att3, const float* __restrict__ b3,
                const float* __restrict__ ln1g, const float* __restrict__ ln1b,
                const float* __restrict__ ln2g, const float* __restrict__ ln2b,
                float* __restrict__ outg)
{
    extern __shared__ float sm[];
    float* hT     = sm;                // 128*66 = 8448
    float* xln    = hT + 8448;         // 64*130 = 8320
    float* xrn    = xln + 8320;        // 8320
    float* eBuf   = xrn + 8320;        // 16384 (layout [h][i][j])
    float* SLa    = eBuf + 16384;      // 256  ([h*64+i])
    float* SRa    = SLa + 256;         // 256
    float* attS   = SRa + 256;         // 128
    float* att04S = attS + 128;        // 128
    float* biasS  = att04S + 128;      // 128
    float* invS   = biasS + 128;       // 256  ([h*64+j])
    float* finS   = invS + 256;        // 1024
    float* impS   = finS + 1024;       // 64
    // total 43712 floats = 174848 B

    const int tid = threadIdx.x;
    const int b   = blockIdx.x;

    // ---------------- Phase 0: build fin (64x16) + importance flags ----------------
    if (tid < 64) {
        float ok;
        if (tid < 16) ok = (team_mask[b * 32 + tid] != NEGV) ? 1.0f : 0.0f;
        else          ok = (ltm[b * 49 + (tid - 16)] != 0.0f) ? 1.0f : 0.0f;
        impS[tid] = ok;
    }
    for (int idx = tid; idx < 1024; idx += 512) {
        int m = idx >> 4, k = idx & 15;
        float v = 0.0f;
        if (m < 16) {
            if (k < 14) v = team_obs[(b * 16 + m) * 14 + k];
        } else {
            int t = m - 16;
            const float* src = &target_obs[(b * 48 + t) * 15];
            if (k < 12)       v = src[k];
            else if (k == 14) v = src[12];
            else if (k == 15) v = src[13];
        }
        finS[idx] = v;
    }
    __syncthreads();

    // ---------------- Phase 1: embedding h = fin @ W_emb + b_emb -> hT (transposed) ----------------
    {
        int f = tid & 127, g = tid >> 7;
        float wc[16];
        #pragma unroll
        for (int k = 0; k < 16; k++) wc[k] = W_emb[k * 128 + f];
        float bb = b_emb[f];
        #pragma unroll 4
        for (int t = 0; t < 16; t++) {
            int m = g + 4 * t;
            float acc = bb;
            const float* fr = &finS[m * 16];
            #pragma unroll
            for (int k = 0; k < 16; k++) acc = fmaf(fr[k], wc[k], acc);
            hT[f * HTS + m] = acc;
        }
    }
    __syncthreads();

    layer_body<128, 4, false>(hT, xln, xrn, eBuf, SLa, SRa, attS, att04S, biasS, invS, impS,
                              Wl1, Wr1, att1, b1, ln1g, ln1b, nullptr, b, tid);
    layer_body<128, 4, false>(hT, xln, xrn, eBuf, SLa, SRa, attS, att04S, biasS, invS, impS,
                              Wl2, Wr2, att2, b2, ln2g, ln2b, nullptr, b, tid);
    layer_body<64, 1, true>(hT, xln, xrn, eBuf, SLa, SRa, attS, att04S, biasS, invS, impS,
                            Wl3, Wr3, att3, b3, nullptr, nullptr, outg, b, tid);
}

extern "C" void kernel_launch(void* const* d_in, const int* in_sizes, int n_in,
                              void* d_out, int out_size) {
    (void)in_sizes; (void)n_in; (void)out_size;
    const size_t smem = 43712u * sizeof(float);
    cudaFuncSetAttribute(GNN_kernel, cudaFuncAttributeMaxDynamicSharedMemorySize, (int)smem);
    GNN_kernel<<<128, 512, smem>>>(
        (const float*)d_in[0],  (const float*)d_in[1],  (const float*)d_in[2],
        (const float*)d_in[3],  (const float*)d_in[4],  (const float*)d_in[5],
        (const float*)d_in[6],  (const float*)d_in[7],  (const float*)d_in[8],
        (const float*)d_in[9],  (const float*)d_in[10], (const float*)d_in[11],
        (const float*)d_in[12], (const float*)d_in[13], (const float*)d_in[14],
        (const float*)d_in[15], (const float*)d_in[16], (const float*)d_in[17],
        (const float*)d_in[18], (const float*)d_in[19], (const float*)d_in[20],
        (const float*)d_in[21], (float*)d_out);
}